// round 1
// baseline (speedup 1.0000x reference)
#include <cuda_runtime.h>
#include <cstdint>
#include <math.h>

// ---------------- problem constants ----------------
namespace {
constexpr int Bb    = 8;
constexpr int Ss    = 1024;
constexpr int FIN   = 256;
constexpr int Ee    = 512;
constexpr int INNER = 1024;
constexpr int NHh   = 4;
constexpr int DHd   = 256;
constexpr int KSk   = 4;
constexpr int ROWS  = Bb * Ss;      // 8192
constexpr int BNH   = Bb * NHh;     // 32
}

// ---------------- scratch (device globals; no runtime alloc) ----------------
__device__ float g_xp[(size_t)ROWS * Ee];
__device__ float g_h [(size_t)ROWS * Ee];
__device__ float g_up[(size_t)ROWS * 2 * INNER];
__device__ float g_xc[(size_t)ROWS * INNER];
__device__ float g_q [(size_t)ROWS * INNER];
__device__ float g_k [(size_t)ROWS * INNER];
__device__ float g_v [(size_t)ROWS * INNER];
__device__ float g_ig[BNH * Ss];
__device__ float g_fg[BNH * Ss];
__device__ float g_e [BNH * Ss];
__device__ float g_pm[BNH * Ss];
__device__ float g_md[BNH * Ss];
__device__ float g_C [(size_t)BNH * Ss * Ss];      // 128 MB
__device__ float g_hh[(size_t)BNH * Ss * DHd];
__device__ float g_hs[(size_t)ROWS * INNER];
__device__ float g_y [(size_t)ROWS * Ee];

// ---------------- helpers ----------------
__device__ __forceinline__ float blockReduceSum(float v) {
    __shared__ float sh[33];
    int lane = threadIdx.x & 31, wid = threadIdx.x >> 5;
    #pragma unroll
    for (int o = 16; o; o >>= 1) v += __shfl_down_sync(0xffffffffu, v, o);
    if (lane == 0) sh[wid] = v;
    __syncthreads();
    int nw = blockDim.x >> 5;
    float t = (threadIdx.x < nw) ? sh[threadIdx.x] : 0.f;
    if (wid == 0) {
        #pragma unroll
        for (int o = 16; o; o >>= 1) t += __shfl_down_sync(0xffffffffu, t, o);
        if (lane == 0) sh[32] = t;
    }
    __syncthreads();
    float r = sh[32];
    __syncthreads();
    return r;
}

// ---------------- generic 128x128x8 SGEMM: C = A (M,K) * op(B) [+bias] ----
// TRANSB=1: B is (N,K) row-major (C = A*B^T). TRANSB=0: B is (K,N) row-major.
// Batched via blockIdx.z; per-batch offsets computed as (z>>2)*OffB + (z&3)*OffN.
// All dims assumed multiples of tile sizes (true for every call here).
template<int TRANSB>
__global__ void __launch_bounds__(256)
gemm128(const float* __restrict__ Ag, const float* __restrict__ Bg,
        float* __restrict__ Cg, const float* __restrict__ bias,
        int K, int lda, int ldb, int ldc,
        long aOffB, long aOffN, long bOffB, long bOffN, long cOffB, long cOffN) {
    int z = blockIdx.z;
    const float* A  = Ag + (long)(z >> 2) * aOffB + (long)(z & 3) * aOffN;
    const float* Bp = Bg + (long)(z >> 2) * bOffB + (long)(z & 3) * bOffN;
    float*       Cp = Cg + (long)(z >> 2) * cOffB + (long)(z & 3) * cOffN;

    __shared__ float As[8][128];
    __shared__ float Bs[8][128];

    int tid = threadIdx.x;
    int tx = tid & 15, ty = tid >> 4;
    long m0 = (long)blockIdx.y * 128, n0 = (long)blockIdx.x * 128;
    int aRow = tid >> 1, aCol = (tid & 1) * 4;
    int bkr  = tid >> 5, bnc  = (tid & 31) * 4;

    float acc[8][8] = {};

    for (int k0 = 0; k0 < K; k0 += 8) {
        float4 av = *(const float4*)(A + (m0 + aRow) * lda + k0 + aCol);
        As[aCol + 0][aRow] = av.x; As[aCol + 1][aRow] = av.y;
        As[aCol + 2][aRow] = av.z; As[aCol + 3][aRow] = av.w;
        if (TRANSB) {
            float4 bv = *(const float4*)(Bp + (n0 + aRow) * ldb + k0 + aCol);
            Bs[aCol + 0][aRow] = bv.x; Bs[aCol + 1][aRow] = bv.y;
            Bs[aCol + 2][aRow] = bv.z; Bs[aCol + 3][aRow] = bv.w;
        } else {
            *(float4*)&Bs[bkr][bnc] =
                *(const float4*)(Bp + (long)(k0 + bkr) * ldb + n0 + bnc);
        }
        __syncthreads();
        #pragma unroll
        for (int kk = 0; kk < 8; ++kk) {
            float a[8], b[8];
            *(float4*)&a[0] = *(float4*)&As[kk][ty * 8];
            *(float4*)&a[4] = *(float4*)&As[kk][ty * 8 + 4];
            *(float4*)&b[0] = *(float4*)&Bs[kk][tx * 8];
            *(float4*)&b[4] = *(float4*)&Bs[kk][tx * 8 + 4];
            #pragma unroll
            for (int i = 0; i < 8; ++i)
                #pragma unroll
                for (int j = 0; j < 8; ++j)
                    acc[i][j] += a[i] * b[j];
        }
        __syncthreads();
    }

    float bcol[8];
    #pragma unroll
    for (int j = 0; j < 8; ++j) bcol[j] = bias ? bias[n0 + tx * 8 + j] : 0.f;

    #pragma unroll
    for (int i = 0; i < 8; ++i) {
        float* cp = Cp + (m0 + ty * 8 + i) * ldc + n0 + tx * 8;
        #pragma unroll
        for (int j = 0; j < 8; j += 4) {
            float4 v;
            v.x = acc[i][j + 0] + bcol[j + 0];
            v.y = acc[i][j + 1] + bcol[j + 1];
            v.z = acc[i][j + 2] + bcol[j + 2];
            v.w = acc[i][j + 3] + bcol[j + 3];
            *(float4*)(cp + j) = v;
        }
    }
}

// ---------------- row LayerNorm (width W), out = (x-mu)*rsqrt(var+eps)*w ----
__global__ void ln_rows(const float* __restrict__ in, const float* __restrict__ w,
                        float* __restrict__ out, int W) {
    long row = blockIdx.x;
    const float* p = in + row * (long)W;
    float s = 0.f, s2 = 0.f;
    for (int j = threadIdx.x; j < W; j += blockDim.x) { float v = p[j]; s += v; s2 += v * v; }
    s  = blockReduceSum(s);
    s2 = blockReduceSum(s2);
    float mu  = s / W;
    float var = s2 / W - mu * mu;
    float r = rsqrtf(var + 1e-5f);
    for (int j = threadIdx.x; j < W; j += blockDim.x)
        out[row * (long)W + j] = (p[j] - mu) * r * w[j];
}

// ---------------- causal depthwise conv (KS=4) + SiLU on x_m -> g_xc -------
__global__ void conv_silu(const float* __restrict__ cw, const float* __restrict__ cb) {
    long idx = (long)blockIdx.x * blockDim.x + threadIdx.x;
    if (idx >= (long)ROWS * INNER) return;
    int  c   = (int)(idx & (INNER - 1));
    long row = idx >> 10;                 // b*S + t
    int  t   = (int)(row & (Ss - 1));
    float acc = cb[c];
    #pragma unroll
    for (int j = 0; j < KSk; ++j) {
        int dt = j - (KSk - 1);
        if (t + dt >= 0)
            acc += g_up[(row + dt) * (2 * INNER) + c] * cw[c * KSk + j];
    }
    g_xc[idx] = acc / (1.f + expf(-acc));
}

// ---------------- blockwise (4x4) q,k from xc; v from x_m ------------------
__global__ void headwise(const float* __restrict__ Wq, const float* __restrict__ Wk,
                         const float* __restrict__ Wv) {
    long idx = (long)blockIdx.x * blockDim.x + threadIdx.x;    // ROWS*256
    if (idx >= (long)ROWS * 256) return;
    int  nb  = (int)(idx & 255);
    long row = idx >> 8;
    long base = row * INNER + nb * 4;
    float xc4[4], xm4[4];
    #pragma unroll
    for (int i = 0; i < 4; ++i) {
        xc4[i] = g_xc[base + i];
        xm4[i] = g_up[row * (2 * INNER) + nb * 4 + i];
    }
    #pragma unroll
    for (int o = 0; o < 4; ++o) {
        float q = 0.f, k = 0.f, v = 0.f;
        #pragma unroll
        for (int i = 0; i < 4; ++i) {
            q += xc4[i] * Wq[nb * 16 + o * 4 + i];
            k += xc4[i] * Wk[nb * 16 + o * 4 + i];
            v += xm4[i] * Wv[nb * 16 + o * 4 + i];
        }
        g_q[base + o] = q; g_k[base + o] = k; g_v[base + o] = v;
    }
}

// ---------------- input/forget gate projections (K=3072, N=4 each) ---------
__global__ void gates(const float* __restrict__ Wig, const float* __restrict__ big,
                      const float* __restrict__ Wfg, const float* __restrict__ bfg) {
    long row = blockIdx.x;   // b*S + s
    float aI[4] = {0, 0, 0, 0}, aF[4] = {0, 0, 0, 0};
    for (int c = threadIdx.x; c < INNER; c += blockDim.x) {
        float qv = g_q[row * INNER + c];
        float kv = g_k[row * INNER + c];
        float vv = g_v[row * INNER + c];
        #pragma unroll
        for (int n = 0; n < 4; ++n) {
            const float* wi = Wig + (long)n * 3 * INNER;
            const float* wf = Wfg + (long)n * 3 * INNER;
            aI[n] += qv * wi[c] + kv * wi[INNER + c] + vv * wi[2 * INNER + c];
            aF[n] += qv * wf[c] + kv * wf[INNER + c] + vv * wf[2 * INNER + c];
        }
    }
    int b = (int)(row >> 10), s = (int)(row & 1023);
    #pragma unroll
    for (int n = 0; n < 4; ++n) {
        float si = blockReduceSum(aI[n]);
        float sf = blockReduceSum(aF[n]);
        if (threadIdx.x == 0) {
            g_ig[(b * NHh + n) * Ss + s] = si + big[n];
            g_fg[(b * NHh + n) * Ss + s] = sf + bfg[n];
        }
    }
}

// ---------------- serial gate scan: e[t], prefix-max, maxD -----------------
__global__ void gate_scan() {
    int bn = threadIdx.x;
    if (bn >= BNH) return;
    float a = 0.f, pm = -1e30f;
    for (int t = 0; t < Ss; ++t) {
        float f  = g_fg[bn * Ss + t];
        float lf = fminf(f, 0.f) - log1pf(expf(-fabsf(f)));   // log_sigmoid
        a += lf;                                              // a[t+1]
        float e = g_ig[bn * Ss + t] - a;
        pm = fmaxf(pm, e);
        g_e [bn * Ss + t] = e;
        g_pm[bn * Ss + t] = pm;
        g_md[bn * Ss + t] = a + pm;                           // maxD[s]
    }
}

// ---------------- apply decay D, causal mask, row-normalize ----------------
__global__ void dapply() {
    int s  = blockIdx.x;
    int bn = blockIdx.y;
    size_t base = ((size_t)bn * Ss + s) * Ss;
    float pm = g_pm[bn * Ss + s];
    const float scale = 0.0625f;   // 1/sqrt(DH)=1/16
    float vals[4];
    float sum = 0.f;
    #pragma unroll
    for (int l = 0; l < 4; ++l) {
        int t = threadIdx.x + l * 256;
        float v = 0.f;
        if (t <= s)
            v = g_C[base + t] * scale * expf(g_e[bn * Ss + t] - pm);
        vals[l] = v;
        sum += v;
    }
    sum = blockReduceSum(sum);
    float nn  = fmaxf(fabsf(sum), expf(-g_md[bn * Ss + s]));
    float inv = 1.f / (nn + 1e-6f);
    #pragma unroll
    for (int l = 0; l < 4; ++l)
        g_C[base + threadIdx.x + l * 256] = vals[l] * inv;
}

// ---------------- per-head LN + skip + SiLU(z) gate -> h_state -------------
__global__ void mhln_combine(const float* __restrict__ mw, const float* __restrict__ skip) {
    int s  = blockIdx.x;
    int bn = blockIdx.y;
    int b = bn >> 2, n = bn & 3;
    int d = threadIdx.x;             // 256 threads == DH
    size_t hrow = ((size_t)bn * Ss + s) * DHd;
    float x  = g_hh[hrow + d];
    float su = blockReduceSum(x);
    float s2 = blockReduceSum(x * x);
    float mu  = su / DHd;
    float var = s2 / DHd - mu * mu;
    float hn = (x - mu) * rsqrtf(var + 1e-5f) * mw[n * DHd + d];
    int c = n * DHd + d;
    size_t row = (size_t)(b * Ss + s);
    float xc = g_xc[row * INNER + c];
    float z  = g_up[row * (2 * INNER) + INNER + c];
    float sz = z / (1.f + expf(-z));
    g_hs[row * INNER + c] = (hn + skip[c] * xc) * sz;
}

// ---------------- out = LN(res + y, ln_post_w) -> d_out --------------------
__global__ void add_ln_out(const float* __restrict__ w, float* __restrict__ out) {
    long row = blockIdx.x;
    float vals[2];
    float s = 0.f, s2 = 0.f;
    #pragma unroll
    for (int l = 0; l < 2; ++l) {
        int j = threadIdx.x + l * 256;
        float v = g_xp[row * Ee + j] + g_y[row * Ee + j];
        vals[l] = v; s += v; s2 += v * v;
    }
    s  = blockReduceSum(s);
    s2 = blockReduceSum(s2);
    float mu  = s / Ee;
    float var = s2 / Ee - mu * mu;
    float r = rsqrtf(var + 1e-5f);
    #pragma unroll
    for (int l = 0; l < 2; ++l) {
        int j = threadIdx.x + l * 256;
        out[row * Ee + j] = (vals[l] - mu) * r * w[j];
    }
}

// ---------------- launch ----------------------------------------------------
extern "C" void kernel_launch(void* const* d_in, const int* /*in_sizes*/, int /*n_in*/,
                              void* d_out, int /*out_size*/) {
    const float* x         = (const float*)d_in[0];
    const float* W_in      = (const float*)d_in[1];
    const float* b_in      = (const float*)d_in[2];
    const float* ln1_w     = (const float*)d_in[3];
    const float* W_up      = (const float*)d_in[4];
    const float* conv_w    = (const float*)d_in[5];
    const float* conv_b    = (const float*)d_in[6];
    const float* Wq        = (const float*)d_in[7];
    const float* Wk        = (const float*)d_in[8];
    const float* Wv        = (const float*)d_in[9];
    const float* W_ig      = (const float*)d_in[10];
    const float* b_ig      = (const float*)d_in[11];
    const float* W_fg      = (const float*)d_in[12];
    const float* b_fg      = (const float*)d_in[13];
    const float* mhln_w    = (const float*)d_in[14];
    const float* skip      = (const float*)d_in[15];
    const float* W_down    = (const float*)d_in[16];
    const float* ln_post_w = (const float*)d_in[17];
    float* out = (float*)d_out;

    void *pxp, *ph, *pup, *pxc, *pq, *pk, *pv, *pC, *phh, *phs, *py;
    cudaGetSymbolAddress(&pxp, g_xp);
    cudaGetSymbolAddress(&ph,  g_h);
    cudaGetSymbolAddress(&pup, g_up);
    cudaGetSymbolAddress(&pxc, g_xc);
    cudaGetSymbolAddress(&pq,  g_q);
    cudaGetSymbolAddress(&pk,  g_k);
    cudaGetSymbolAddress(&pv,  g_v);
    cudaGetSymbolAddress(&pC,  g_C);
    cudaGetSymbolAddress(&phh, g_hh);
    cudaGetSymbolAddress(&phs, g_hs);
    cudaGetSymbolAddress(&py,  g_y);

    // 1. xp = x @ W_in^T + b_in        (M=8192, N=512, K=256)
    gemm128<1><<<dim3(Ee / 128, ROWS / 128, 1), 256>>>(
        x, W_in, (float*)pxp, b_in, FIN, FIN, FIN, Ee, 0, 0, 0, 0, 0, 0);

    // 2. h = LN(xp)
    ln_rows<<<ROWS, 256>>>((const float*)pxp, ln1_w, (float*)ph, Ee);

    // 3. up = h @ W_up^T               (M=8192, N=2048, K=512)
    gemm128<1><<<dim3(2 * INNER / 128, ROWS / 128, 1), 256>>>(
        (const float*)ph, W_up, (float*)pup, nullptr, Ee, Ee, Ee, 2 * INNER,
        0, 0, 0, 0, 0, 0);

    // 4. xc = silu(causal_conv(x_m))
    conv_silu<<<(ROWS * INNER) / 256, 256>>>(conv_w, conv_b);

    // 5. q,k (from xc), v (from x_m) blockwise 4x4
    headwise<<<(ROWS * 256) / 256, 256>>>(Wq, Wk, Wv);

    // 6. ig, fg gate projections
    gates<<<ROWS, 256>>>(W_ig, b_ig, W_fg, b_fg);

    // 7. gate scan (log-sigmoid cumsum, prefix max, maxD)
    gate_scan<<<1, 32>>>();

    // 8. C0 = q @ k^T per head        (32 x [1024,1024,256])
    gemm128<1><<<dim3(Ss / 128, Ss / 128, BNH), 256>>>(
        (const float*)pq, (const float*)pk, (float*)pC, nullptr,
        DHd, INNER, INNER, Ss,
        (long)Ss * INNER, (long)DHd,
        (long)Ss * INNER, (long)DHd,
        4L * Ss * Ss, (long)Ss * Ss);

    // 9. apply decay matrix, causal mask, normalizer
    dapply<<<dim3(Ss, BNH), 256>>>();

    // 10. hh = Cn @ v per head        (32 x [1024,256,1024])
    gemm128<0><<<dim3(DHd / 128, Ss / 128, BNH), 256>>>(
        (const float*)pC, (const float*)pv, (float*)phh, nullptr,
        Ss, Ss, INNER, DHd,
        4L * Ss * Ss, (long)Ss * Ss,
        (long)Ss * INNER, (long)DHd,
        4L * Ss * DHd, (long)Ss * DHd);

    // 11. per-head LN + combine with skip*xc and silu(z)
    mhln_combine<<<dim3(Ss, BNH), 256>>>(mhln_w, skip);

    // 12. y = h_state @ W_down^T       (M=8192, N=512, K=1024)
    gemm128<1><<<dim3(Ee / 128, ROWS / 128, 1), 256>>>(
        (const float*)phs, W_down, (float*)py, nullptr, INNER, INNER, INNER, Ee,
        0, 0, 0, 0, 0, 0);

    // 13. out = LN(res + y)
    add_ln_out<<<ROWS, 256>>>(ln_post_w, out);
}

// round 2
// speedup vs baseline: 1.0121x; 1.0121x over previous
#include <cuda_runtime.h>
#include <cstdint>
#include <math.h>

// ---------------- problem constants ----------------
namespace {
constexpr int Bb    = 8;
constexpr int Ss    = 1024;
constexpr int FIN   = 256;
constexpr int Ee    = 512;
constexpr int INNER = 1024;
constexpr int NHh   = 4;
constexpr int DHd   = 256;
constexpr int KSk   = 4;
constexpr int ROWS  = Bb * Ss;      // 8192
constexpr int BNH   = Bb * NHh;     // 32
}

// ---------------- scratch (device globals; no runtime alloc) ----------------
__device__ float g_xp[(size_t)ROWS * Ee];
__device__ float g_h [(size_t)ROWS * Ee];
__device__ float g_up[(size_t)ROWS * 2 * INNER];
__device__ float g_xc[(size_t)ROWS * INNER];
__device__ float g_q [(size_t)ROWS * INNER];
__device__ float g_k [(size_t)ROWS * INNER];
__device__ float g_v [(size_t)ROWS * INNER];
__device__ float g_ig[BNH * Ss];
__device__ float g_fg[BNH * Ss];
__device__ float g_e [BNH * Ss];
__device__ float g_pm[BNH * Ss];
__device__ float g_md[BNH * Ss];
__device__ float g_C [(size_t)BNH * Ss * Ss];      // 128 MB
__device__ float g_hh[(size_t)BNH * Ss * DHd];
__device__ float g_hs[(size_t)ROWS * INNER];
__device__ float g_y [(size_t)ROWS * Ee];

// ---------------- packed f32x2 helpers (Blackwell FFMA2) -------------------
__device__ __forceinline__ void fma_f32x2(unsigned long long& d,
                                          unsigned long long a,
                                          unsigned long long b,
                                          unsigned long long c) {
    asm("fma.rn.f32x2 %0, %1, %2, %3;" : "=l"(d) : "l"(a), "l"(b), "l"(c));
}
__device__ __forceinline__ unsigned long long packdup(float f) {
    unsigned long long d;
    unsigned u = __float_as_uint(f);
    asm("mov.b64 %0, {%1, %1};" : "=l"(d) : "r"(u));
    return d;
}
__device__ __forceinline__ void unpack2(unsigned long long v, float& lo, float& hi) {
    unsigned a, b;
    asm("mov.b64 {%0, %1}, %2;" : "=r"(a), "=r"(b) : "l"(v));
    lo = __uint_as_float(a);
    hi = __uint_as_float(b);
}

// ---------------- helpers ----------------
__device__ __forceinline__ float blockReduceSum(float v) {
    __shared__ float sh[33];
    int lane = threadIdx.x & 31, wid = threadIdx.x >> 5;
    #pragma unroll
    for (int o = 16; o; o >>= 1) v += __shfl_down_sync(0xffffffffu, v, o);
    if (lane == 0) sh[wid] = v;
    __syncthreads();
    int nw = blockDim.x >> 5;
    float t = (threadIdx.x < nw) ? sh[threadIdx.x] : 0.f;
    if (wid == 0) {
        #pragma unroll
        for (int o = 16; o; o >>= 1) t += __shfl_down_sync(0xffffffffu, t, o);
        if (lane == 0) sh[32] = t;
    }
    __syncthreads();
    float r = sh[32];
    __syncthreads();
    return r;
}

// ---------------- 128x128x8 SGEMM with FFMA2 + double buffering ------------
// C = A (M,K) * op(B) [+bias]
// TRANSB=1: B is (N,K) row-major (C = A*B^T). TRANSB=0: B is (K,N) row-major.
// Batched via blockIdx.z; per-batch offsets: (z>>2)*OffB + (z&3)*OffN.
template<int TRANSB>
__global__ void __launch_bounds__(256, 2)
gemm128(const float* __restrict__ Ag, const float* __restrict__ Bg,
        float* __restrict__ Cg, const float* __restrict__ bias,
        int K, int lda, int ldb, int ldc,
        long aOffB, long aOffN, long bOffB, long bOffN, long cOffB, long cOffN) {
    int z = blockIdx.z;
    const float* A  = Ag + (long)(z >> 2) * aOffB + (long)(z & 3) * aOffN;
    const float* Bp = Bg + (long)(z >> 2) * bOffB + (long)(z & 3) * bOffN;
    float*       Cp = Cg + (long)(z >> 2) * cOffB + (long)(z & 3) * cOffN;

    __shared__ float As[2][8][128];
    __shared__ float Bs[2][8][128];

    int tid = threadIdx.x;
    int tx = tid & 15, ty = tid >> 4;
    long m0 = (long)blockIdx.y * 128, n0 = (long)blockIdx.x * 128;
    int aRow = tid >> 1, aCol = (tid & 1) * 4;
    int bkr  = tid >> 5, bnc  = (tid & 31) * 4;

    // packed accumulators: acc[i2][j] holds C rows (ty*8+2*i2, ty*8+2*i2+1), col tx*8+j
    unsigned long long acc[4][8] = {};

    const int nTiles = K >> 3;

    // prologue: tile 0 -> buffer 0
    {
        float4 av = *(const float4*)(A + (m0 + aRow) * lda + 0 + aCol);
        As[0][aCol + 0][aRow] = av.x; As[0][aCol + 1][aRow] = av.y;
        As[0][aCol + 2][aRow] = av.z; As[0][aCol + 3][aRow] = av.w;
        if (TRANSB) {
            float4 bv = *(const float4*)(Bp + (n0 + aRow) * ldb + 0 + aCol);
            Bs[0][aCol + 0][aRow] = bv.x; Bs[0][aCol + 1][aRow] = bv.y;
            Bs[0][aCol + 2][aRow] = bv.z; Bs[0][aCol + 3][aRow] = bv.w;
        } else {
            *(float4*)&Bs[0][bkr][bnc] = *(const float4*)(Bp + (long)bkr * ldb + n0 + bnc);
        }
    }
    __syncthreads();

    for (int t = 0; t < nTiles; ++t) {
        int cur = t & 1, nxt = cur ^ 1;
        float4 avp, bvp;
        bool more = (t + 1 < nTiles);
        if (more) {
            int k0 = (t + 1) << 3;
            avp = *(const float4*)(A + (m0 + aRow) * lda + k0 + aCol);
            if (TRANSB)
                bvp = *(const float4*)(Bp + (n0 + aRow) * ldb + k0 + aCol);
            else
                bvp = *(const float4*)(Bp + (long)(k0 + bkr) * ldb + n0 + bnc);
        }

        #pragma unroll
        for (int kk = 0; kk < 8; ++kk) {
            // a row-pairs: contiguous in smem -> load as packed 64-bit directly
            ulonglong2 a01 = *(const ulonglong2*)&As[cur][kk][ty * 8];
            ulonglong2 a23 = *(const ulonglong2*)&As[cur][kk][ty * 8 + 4];
            unsigned long long a2[4] = {a01.x, a01.y, a23.x, a23.y};
            float b[8];
            *(float4*)&b[0] = *(float4*)&Bs[cur][kk][tx * 8];
            *(float4*)&b[4] = *(float4*)&Bs[cur][kk][tx * 8 + 4];
            unsigned long long bd[8];
            #pragma unroll
            for (int j = 0; j < 8; ++j) bd[j] = packdup(b[j]);   // ALU pipe
            #pragma unroll
            for (int i2 = 0; i2 < 4; ++i2)
                #pragma unroll
                for (int j = 0; j < 8; ++j)
                    fma_f32x2(acc[i2][j], a2[i2], bd[j], acc[i2][j]);
        }

        if (more) {
            As[nxt][aCol + 0][aRow] = avp.x; As[nxt][aCol + 1][aRow] = avp.y;
            As[nxt][aCol + 2][aRow] = avp.z; As[nxt][aCol + 3][aRow] = avp.w;
            if (TRANSB) {
                Bs[nxt][aCol + 0][aRow] = bvp.x; Bs[nxt][aCol + 1][aRow] = bvp.y;
                Bs[nxt][aCol + 2][aRow] = bvp.z; Bs[nxt][aCol + 3][aRow] = bvp.w;
            } else {
                *(float4*)&Bs[nxt][bkr][bnc] = bvp;
            }
        }
        __syncthreads();
    }

    float bcol[8];
    #pragma unroll
    for (int j = 0; j < 8; ++j) bcol[j] = bias ? bias[n0 + tx * 8 + j] : 0.f;

    #pragma unroll
    for (int i2 = 0; i2 < 4; ++i2) {
        float lo[8], hi[8];
        #pragma unroll
        for (int j = 0; j < 8; ++j) unpack2(acc[i2][j], lo[j], hi[j]);
        long r0 = m0 + ty * 8 + 2 * i2;
        float* c0 = Cp + r0 * ldc + n0 + tx * 8;
        float* c1 = c0 + ldc;
        #pragma unroll
        for (int j = 0; j < 8; j += 4) {
            float4 v0, v1;
            v0.x = lo[j+0]+bcol[j+0]; v0.y = lo[j+1]+bcol[j+1];
            v0.z = lo[j+2]+bcol[j+2]; v0.w = lo[j+3]+bcol[j+3];
            v1.x = hi[j+0]+bcol[j+0]; v1.y = hi[j+1]+bcol[j+1];
            v1.z = hi[j+2]+bcol[j+2]; v1.w = hi[j+3]+bcol[j+3];
            *(float4*)(c0 + j) = v0;
            *(float4*)(c1 + j) = v1;
        }
    }
}

// ---------------- row LayerNorm (width W) ----------------------------------
__global__ void ln_rows(const float* __restrict__ in, const float* __restrict__ w,
                        float* __restrict__ out, int W) {
    long row = blockIdx.x;
    const float* p = in + row * (long)W;
    float s = 0.f, s2 = 0.f;
    for (int j = threadIdx.x; j < W; j += blockDim.x) { float v = p[j]; s += v; s2 += v * v; }
    s  = blockReduceSum(s);
    s2 = blockReduceSum(s2);
    float mu  = s / W;
    float var = s2 / W - mu * mu;
    float r = rsqrtf(var + 1e-5f);
    for (int j = threadIdx.x; j < W; j += blockDim.x)
        out[row * (long)W + j] = (p[j] - mu) * r * w[j];
}

// ---------------- causal depthwise conv (KS=4) + SiLU -> g_xc --------------
__global__ void conv_silu(const float* __restrict__ cw, const float* __restrict__ cb) {
    long idx = (long)blockIdx.x * blockDim.x + threadIdx.x;
    if (idx >= (long)ROWS * INNER) return;
    int  c   = (int)(idx & (INNER - 1));
    long row = idx >> 10;                 // b*S + t
    int  t   = (int)(row & (Ss - 1));
    float acc = cb[c];
    #pragma unroll
    for (int j = 0; j < KSk; ++j) {
        int dt = j - (KSk - 1);
        if (t + dt >= 0)
            acc += g_up[(row + dt) * (2 * INNER) + c] * cw[c * KSk + j];
    }
    g_xc[idx] = acc / (1.f + expf(-acc));
}

// ---------------- blockwise (4x4) q,k from xc; v from x_m ------------------
__global__ void headwise(const float* __restrict__ Wq, const float* __restrict__ Wk,
                         const float* __restrict__ Wv) {
    long idx = (long)blockIdx.x * blockDim.x + threadIdx.x;    // ROWS*256
    if (idx >= (long)ROWS * 256) return;
    int  nb  = (int)(idx & 255);
    long row = idx >> 8;
    long base = row * INNER + nb * 4;
    float xc4[4], xm4[4];
    #pragma unroll
    for (int i = 0; i < 4; ++i) {
        xc4[i] = g_xc[base + i];
        xm4[i] = g_up[row * (2 * INNER) + nb * 4 + i];
    }
    #pragma unroll
    for (int o = 0; o < 4; ++o) {
        float q = 0.f, k = 0.f, v = 0.f;
        #pragma unroll
        for (int i = 0; i < 4; ++i) {
            q += xc4[i] * Wq[nb * 16 + o * 4 + i];
            k += xc4[i] * Wk[nb * 16 + o * 4 + i];
            v += xm4[i] * Wv[nb * 16 + o * 4 + i];
        }
        g_q[base + o] = q; g_k[base + o] = k; g_v[base + o] = v;
    }
}

// ---------------- input/forget gate projections (K=3072, N=4 each) ---------
__global__ void gates(const float* __restrict__ Wig, const float* __restrict__ big,
                      const float* __restrict__ Wfg, const float* __restrict__ bfg) {
    long row = blockIdx.x;   // b*S + s
    float aI[4] = {0, 0, 0, 0}, aF[4] = {0, 0, 0, 0};
    for (int c = threadIdx.x; c < INNER; c += blockDim.x) {
        float qv = g_q[row * INNER + c];
        float kv = g_k[row * INNER + c];
        float vv = g_v[row * INNER + c];
        #pragma unroll
        for (int n = 0; n < 4; ++n) {
            const float* wi = Wig + (long)n * 3 * INNER;
            const float* wf = Wfg + (long)n * 3 * INNER;
            aI[n] += qv * wi[c] + kv * wi[INNER + c] + vv * wi[2 * INNER + c];
            aF[n] += qv * wf[c] + kv * wf[INNER + c] + vv * wf[2 * INNER + c];
        }
    }
    int b = (int)(row >> 10), s = (int)(row & 1023);
    #pragma unroll
    for (int n = 0; n < 4; ++n) {
        float si = blockReduceSum(aI[n]);
        float sf = blockReduceSum(aF[n]);
        if (threadIdx.x == 0) {
            g_ig[(b * NHh + n) * Ss + s] = si + big[n];
            g_fg[(b * NHh + n) * Ss + s] = sf + bfg[n];
        }
    }
}

// ---------------- serial gate scan: e[t], prefix-max, maxD -----------------
__global__ void gate_scan() {
    int bn = threadIdx.x;
    if (bn >= BNH) return;
    float a = 0.f, pm = -1e30f;
    for (int t = 0; t < Ss; ++t) {
        float f  = g_fg[bn * Ss + t];
        float lf = fminf(f, 0.f) - log1pf(expf(-fabsf(f)));   // log_sigmoid
        a += lf;                                              // a[t+1]
        float e = g_ig[bn * Ss + t] - a;
        pm = fmaxf(pm, e);
        g_e [bn * Ss + t] = e;
        g_pm[bn * Ss + t] = pm;
        g_md[bn * Ss + t] = a + pm;                           // maxD[s]
    }
}

// ---------------- apply decay D, causal mask, row-normalize ----------------
__global__ void dapply() {
    int s  = blockIdx.x;
    int bn = blockIdx.y;
    size_t base = ((size_t)bn * Ss + s) * Ss;
    float pm = g_pm[bn * Ss + s];
    const float scale = 0.0625f;   // 1/sqrt(DH)=1/16
    float vals[4];
    float sum = 0.f;
    #pragma unroll
    for (int l = 0; l < 4; ++l) {
        int t = threadIdx.x + l * 256;
        float v = 0.f;
        if (t <= s)
            v = g_C[base + t] * scale * expf(g_e[bn * Ss + t] - pm);
        vals[l] = v;
        sum += v;
    }
    sum = blockReduceSum(sum);
    float nn  = fmaxf(fabsf(sum), expf(-g_md[bn * Ss + s]));
    float inv = 1.f / (nn + 1e-6f);
    #pragma unroll
    for (int l = 0; l < 4; ++l)
        g_C[base + threadIdx.x + l * 256] = vals[l] * inv;
}

// ---------------- per-head LN + skip + SiLU(z) gate -> h_state -------------
__global__ void mhln_combine(const float* __restrict__ mw, const float* __restrict__ skip) {
    int s  = blockIdx.x;
    int bn = blockIdx.y;
    int b = bn >> 2, n = bn & 3;
    int d = threadIdx.x;             // 256 threads == DH
    size_t hrow = ((size_t)bn * Ss + s) * DHd;
    float x  = g_hh[hrow + d];
    float su = blockReduceSum(x);
    float s2 = blockReduceSum(x * x);
    float mu  = su / DHd;
    float var = s2 / DHd - mu * mu;
    float hn = (x - mu) * rsqrtf(var + 1e-5f) * mw[n * DHd + d];
    int c = n * DHd + d;
    size_t row = (size_t)(b * Ss + s);
    float xc = g_xc[row * INNER + c];
    float z  = g_up[row * (2 * INNER) + INNER + c];
    float sz = z / (1.f + expf(-z));
    g_hs[row * INNER + c] = (hn + skip[c] * xc) * sz;
}

// ---------------- out = LN(res + y, ln_post_w) -> d_out --------------------
__global__ void add_ln_out(const float* __restrict__ w, float* __restrict__ out) {
    long row = blockIdx.x;
    float vals[2];
    float s = 0.f, s2 = 0.f;
    #pragma unroll
    for (int l = 0; l < 2; ++l) {
        int j = threadIdx.x + l * 256;
        float v = g_xp[row * Ee + j] + g_y[row * Ee + j];
        vals[l] = v; s += v; s2 += v * v;
    }
    s  = blockReduceSum(s);
    s2 = blockReduceSum(s2);
    float mu  = s / Ee;
    float var = s2 / Ee - mu * mu;
    float r = rsqrtf(var + 1e-5f);
    #pragma unroll
    for (int l = 0; l < 2; ++l) {
        int j = threadIdx.x + l * 256;
        out[row * Ee + j] = (vals[l] - mu) * r * w[j];
    }
}

// ---------------- launch ----------------------------------------------------
extern "C" void kernel_launch(void* const* d_in, const int* /*in_sizes*/, int /*n_in*/,
                              void* d_out, int /*out_size*/) {
    const float* x         = (const float*)d_in[0];
    const float* W_in      = (const float*)d_in[1];
    const float* b_in      = (const float*)d_in[2];
    const float* ln1_w     = (const float*)d_in[3];
    const float* W_up      = (const float*)d_in[4];
    const float* conv_w    = (const float*)d_in[5];
    const float* conv_b    = (const float*)d_in[6];
    const float* Wq        = (const float*)d_in[7];
    const float* Wk        = (const float*)d_in[8];
    const float* Wv        = (const float*)d_in[9];
    const float* W_ig      = (const float*)d_in[10];
    const float* b_ig      = (const float*)d_in[11];
    const float* W_fg      = (const float*)d_in[12];
    const float* b_fg      = (const float*)d_in[13];
    const float* mhln_w    = (const float*)d_in[14];
    const float* skip      = (const float*)d_in[15];
    const float* W_down    = (const float*)d_in[16];
    const float* ln_post_w = (const float*)d_in[17];
    float* out = (float*)d_out;

    void *pxp, *ph, *pup, *pxc, *pq, *pk, *pv, *pC, *phh, *phs, *py;
    cudaGetSymbolAddress(&pxp, g_xp);
    cudaGetSymbolAddress(&ph,  g_h);
    cudaGetSymbolAddress(&pup, g_up);
    cudaGetSymbolAddress(&pxc, g_xc);
    cudaGetSymbolAddress(&pq,  g_q);
    cudaGetSymbolAddress(&pk,  g_k);
    cudaGetSymbolAddress(&pv,  g_v);
    cudaGetSymbolAddress(&pC,  g_C);
    cudaGetSymbolAddress(&phh, g_hh);
    cudaGetSymbolAddress(&phs, g_hs);
    cudaGetSymbolAddress(&py,  g_y);

    // 1. xp = x @ W_in^T + b_in        (M=8192, N=512, K=256)
    gemm128<1><<<dim3(Ee / 128, ROWS / 128, 1), 256>>>(
        x, W_in, (float*)pxp, b_in, FIN, FIN, FIN, Ee, 0, 0, 0, 0, 0, 0);

    // 2. h = LN(xp)
    ln_rows<<<ROWS, 256>>>((const float*)pxp, ln1_w, (float*)ph, Ee);

    // 3. up = h @ W_up^T               (M=8192, N=2048, K=512)
    gemm128<1><<<dim3(2 * INNER / 128, ROWS / 128, 1), 256>>>(
        (const float*)ph, W_up, (float*)pup, nullptr, Ee, Ee, Ee, 2 * INNER,
        0, 0, 0, 0, 0, 0);

    // 4. xc = silu(causal_conv(x_m))
    conv_silu<<<(ROWS * INNER) / 256, 256>>>(conv_w, conv_b);

    // 5. q,k (from xc), v (from x_m) blockwise 4x4
    headwise<<<(ROWS * 256) / 256, 256>>>(Wq, Wk, Wv);

    // 6. ig, fg gate projections
    gates<<<ROWS, 256>>>(W_ig, b_ig, W_fg, b_fg);

    // 7. gate scan (log-sigmoid cumsum, prefix max, maxD)
    gate_scan<<<1, 32>>>();

    // 8. C0 = q @ k^T per head        (32 x [1024,1024,256])
    gemm128<1><<<dim3(Ss / 128, Ss / 128, BNH), 256>>>(
        (const float*)pq, (const float*)pk, (float*)pC, nullptr,
        DHd, INNER, INNER, Ss,
        (long)Ss * INNER, (long)DHd,
        (long)Ss * INNER, (long)DHd,
        4L * Ss * Ss, (long)Ss * Ss);

    // 9. apply decay matrix, causal mask, normalizer
    dapply<<<dim3(Ss, BNH), 256>>>();

    // 10. hh = Cn @ v per head        (32 x [1024,256,1024])
    gemm128<0><<<dim3(DHd / 128, Ss / 128, BNH), 256>>>(
        (const float*)pC, (const float*)pv, (float*)phh, nullptr,
        Ss, Ss, INNER, DHd,
        4L * Ss * Ss, (long)Ss * Ss,
        (long)Ss * INNER, (long)DHd,
        4L * Ss * DHd, (long)Ss * DHd);

    // 11. per-head LN + combine with skip*xc and silu(z)
    mhln_combine<<<dim3(Ss, BNH), 256>>>(mhln_w, skip);

    // 12. y = h_state @ W_down^T       (M=8192, N=512, K=1024)
    gemm128<1><<<dim3(Ee / 128, ROWS / 128, 1), 256>>>(
        (const float*)phs, W_down, (float*)py, nullptr, INNER, INNER, INNER, Ee,
        0, 0, 0, 0, 0, 0);

    // 13. out = LN(res + y)
    add_ln_out<<<ROWS, 256>>>(ln_post_w, out);
}

// round 4
// speedup vs baseline: 1.9340x; 1.9109x over previous
#include <cuda_runtime.h>
#include <cstdint>
#include <math.h>

// ---------------- problem constants ----------------
namespace {
constexpr int Bb    = 8;
constexpr int Ss    = 1024;
constexpr int FIN   = 256;
constexpr int Ee    = 512;
constexpr int INNER = 1024;
constexpr int NHh   = 4;
constexpr int DHd   = 256;
constexpr int KSk   = 4;
constexpr int ROWS  = Bb * Ss;      // 8192
constexpr int BNH   = Bb * NHh;     // 32

// smem tile geometry for the mma GEMM
constexpr int KT      = 32;                  // K per stage
constexpr int ROWSTR  = 36;                  // floats per smem row (pad: banks 4r+c unique)
constexpr int TILE_F  = 128 * ROWSTR;        // floats per A or B tile (4608)
constexpr int STAGE_F = 2 * TILE_F;          // A+B per stage
constexpr int GSMEM   = 2 * STAGE_F * 4;     // bytes (73728)
}

// ---------------- scratch (device globals; no runtime alloc) ----------------
__device__ float g_xp[(size_t)ROWS * Ee];
__device__ float g_h [(size_t)ROWS * Ee];
__device__ float g_up[(size_t)ROWS * 2 * INNER];
__device__ float g_xc[(size_t)ROWS * INNER];
__device__ float g_q [(size_t)ROWS * INNER];
__device__ float g_k [(size_t)ROWS * INNER];
__device__ float g_v [(size_t)ROWS * INNER];
__device__ float g_vT[(size_t)BNH * DHd * Ss];      // per-head v^T (K-major for C*V)
__device__ float g_ig[BNH * Ss];
__device__ float g_fg[BNH * Ss];
__device__ float g_e [BNH * Ss];
__device__ float g_pm[BNH * Ss];
__device__ float g_md[BNH * Ss];
__device__ float g_C [(size_t)BNH * Ss * Ss];       // 128 MB
__device__ float g_hh[(size_t)BNH * Ss * DHd];
__device__ float g_hs[(size_t)ROWS * INNER];
__device__ float g_y [(size_t)ROWS * Ee];
// tf32-rounded copies of GEMM operands we can't round in place
__device__ float g_xr[(size_t)ROWS * FIN];
__device__ float g_Wi[(size_t)Ee * FIN];
__device__ float g_Wu[(size_t)2 * INNER * Ee];
__device__ float g_Wd[(size_t)Ee * INNER];

// ---------------- small helpers ----------------
__device__ __forceinline__ uint32_t smem_u32(const void* p) {
    uint32_t a;
    asm("{ .reg .u64 t; cvta.to.shared.u64 t, %1; cvt.u32.u64 %0, t; }" : "=r"(a) : "l"(p));
    return a;
}
__device__ __forceinline__ float tf32r(float x) {
    uint32_t u;
    asm("cvt.rna.tf32.f32 %0, %1;" : "=r"(u) : "f"(x));
    return __uint_as_float(u);
}
__device__ __forceinline__ void mma_tf32(float* c, const uint32_t* a, const uint32_t* b) {
    asm volatile(
        "mma.sync.aligned.m16n8k8.row.col.f32.tf32.tf32.f32 "
        "{%0,%1,%2,%3}, {%4,%5,%6,%7}, {%8,%9}, {%0,%1,%2,%3};"
        : "+f"(c[0]), "+f"(c[1]), "+f"(c[2]), "+f"(c[3])
        : "r"(a[0]), "r"(a[1]), "r"(a[2]), "r"(a[3]), "r"(b[0]), "r"(b[1]));
}
#define CP16(dst, src) \
    asm volatile("cp.async.cg.shared.global [%0], [%1], 16;" :: "r"(dst), "l"(src) : "memory")
#define CP_COMMIT() asm volatile("cp.async.commit_group;" ::: "memory")
#define CP_WAIT(n)  asm volatile("cp.async.wait_group %0;" :: "n"(n) : "memory")

// ---------------- block reduce ----------------
__device__ __forceinline__ float blockReduceSum(float v) {
    __shared__ float sh[33];
    int lane = threadIdx.x & 31, wid = threadIdx.x >> 5;
    #pragma unroll
    for (int o = 16; o; o >>= 1) v += __shfl_down_sync(0xffffffffu, v, o);
    if (lane == 0) sh[wid] = v;
    __syncthreads();
    int nw = blockDim.x >> 5;
    float t = (threadIdx.x < nw) ? sh[threadIdx.x] : 0.f;
    if (wid == 0) {
        #pragma unroll
        for (int o = 16; o; o >>= 1) t += __shfl_down_sync(0xffffffffu, t, o);
        if (lane == 0) sh[32] = t;
    }
    __syncthreads();
    float r = sh[32];
    __syncthreads();
    return r;
}

// ---------------- warp-MMA tf32 GEMM: C = A(M,K) * B(N,K)^T [+bias] --------
// TRI=0: full. TRI=1: skip CTAs with bx>by (causal upper triangle).
// TRI=2: limit K to (by+1)*128 (block-lower-triangular A).
// batch decode: z -> (z>>2)*OffB + (z&3)*OffN
template<int TRI>
__global__ void __launch_bounds__(256)
mma_gemm(const float* __restrict__ Ag, const float* __restrict__ Bg,
         float* __restrict__ Cg, const float* __restrict__ bias,
         int K, int lda, int ldb, int ldc,
         long aOffB, long aOffN, long bOffB, long bOffN, long cOffB, long cOffN) {
    int bx = blockIdx.x, by = blockIdx.y, z = blockIdx.z;
    if (TRI == 1 && bx > by) return;
    extern __shared__ float sm[];
    uint32_t sb = smem_u32(sm);
    int tid = threadIdx.x;

    const float* A = Ag + (long)(z >> 2) * aOffB + (long)(z & 3) * aOffN + (long)by * 128 * lda;
    const float* B = Bg + (long)(z >> 2) * bOffB + (long)(z & 3) * bOffN + (long)bx * 128 * ldb;
    float*       Cp = Cg + (long)(z >> 2) * cOffB + (long)(z & 3) * cOffN;

    int Keff = (TRI == 2) ? min(K, (by + 1) * 128) : K;
    int nT = Keff / KT;

    // loader: thread t -> row = t>>1, four 16B chunks at (t&1)*64B
    int lrow = tid >> 1;
    int lch  = (tid & 1) * 4;
    auto load_tile = [&](int kt, int s) {
        uint32_t abase = sb + (uint32_t)(s * STAGE_F) * 4 + lrow * (ROWSTR * 4);
        uint32_t bbase = abase + TILE_F * 4;
        const float* ap = A + (long)lrow * lda + kt * KT + lch * 4;
        const float* bp = B + (long)lrow * ldb + kt * KT + lch * 4;
        #pragma unroll
        for (int i = 0; i < 4; ++i) {
            CP16(abase + (lch + i) * 16, ap + i * 4);
            CP16(bbase + (lch + i) * 16, bp + i * 4);
        }
    };

    int wid = tid >> 5, lane = tid & 31;
    int wm = wid >> 2, wn = wid & 3;          // 2 x 4 warp grid
    int gid = lane >> 2, tig = lane & 3;

    float acc[4][4][4] = {};                  // [mi][ni][frag]

    load_tile(0, 0);
    CP_COMMIT();

    for (int kt = 0; kt < nT; ++kt) {
        int cur = kt & 1;
        if (kt + 1 < nT) {
            load_tile(kt + 1, cur ^ 1);
            CP_COMMIT();
            CP_WAIT(1);
        } else {
            CP_WAIT(0);
        }
        __syncthreads();

        const float* As = sm + cur * STAGE_F;
        const float* Bs = As + TILE_F;
        #pragma unroll
        for (int ks = 0; ks < 4; ++ks) {
            int kc = ks * 8;
            uint32_t a[4][4], b[4][2];
            #pragma unroll
            for (int mi = 0; mi < 4; ++mi) {
                int r = wm * 64 + mi * 16 + gid;
                a[mi][0] = __float_as_uint(As[r * ROWSTR + kc + tig]);
                a[mi][1] = __float_as_uint(As[(r + 8) * ROWSTR + kc + tig]);
                a[mi][2] = __float_as_uint(As[r * ROWSTR + kc + tig + 4]);
                a[mi][3] = __float_as_uint(As[(r + 8) * ROWSTR + kc + tig + 4]);
            }
            #pragma unroll
            for (int ni = 0; ni < 4; ++ni) {
                int n = wn * 32 + ni * 8 + gid;
                b[ni][0] = __float_as_uint(Bs[n * ROWSTR + kc + tig]);
                b[ni][1] = __float_as_uint(Bs[n * ROWSTR + kc + tig + 4]);
            }
            #pragma unroll
            for (int mi = 0; mi < 4; ++mi)
                #pragma unroll
                for (int ni = 0; ni < 4; ++ni)
                    mma_tf32(acc[mi][ni], a[mi], b[ni]);
        }
        __syncthreads();
    }

    // epilogue
    long m0 = (long)by * 128 + wm * 64;
    long n0 = (long)bx * 128 + wn * 32;
    #pragma unroll
    for (int mi = 0; mi < 4; ++mi) {
        #pragma unroll
        for (int ni = 0; ni < 4; ++ni) {
            long r = m0 + mi * 16 + gid;
            long c = n0 + ni * 8 + tig * 2;
            float b0 = bias ? bias[c] : 0.f, b1 = bias ? bias[c + 1] : 0.f;
            float2 v0 = {acc[mi][ni][0] + b0, acc[mi][ni][1] + b1};
            float2 v1 = {acc[mi][ni][2] + b0, acc[mi][ni][3] + b1};
            *(float2*)(Cp + r * ldc + c) = v0;
            *(float2*)(Cp + (r + 8) * ldc + c) = v1;
        }
    }
}

// ---------------- tf32 rounding copy (vectorized) ---------------------------
__global__ void roundbuf(const float* __restrict__ in, float* __restrict__ out, int n4) {
    int i = blockIdx.x * 256 + threadIdx.x;
    if (i < n4) {
        float4 v = ((const float4*)in)[i];
        v.x = tf32r(v.x); v.y = tf32r(v.y); v.z = tf32r(v.z); v.w = tf32r(v.w);
        ((float4*)out)[i] = v;
    }
}

// ---------------- row LayerNorm (width W); RND=1 rounds output to tf32 -----
template<int RND>
__global__ void ln_rows(const float* __restrict__ in, const float* __restrict__ w,
                        float* __restrict__ out, int W) {
    long row = blockIdx.x;
    const float* p = in + row * (long)W;
    float s = 0.f, s2 = 0.f;
    for (int j = threadIdx.x; j < W; j += blockDim.x) { float v = p[j]; s += v; s2 += v * v; }
    s  = blockReduceSum(s);
    s2 = blockReduceSum(s2);
    float mu  = s / W;
    float var = s2 / W - mu * mu;
    float r = rsqrtf(var + 1e-5f);
    for (int j = threadIdx.x; j < W; j += blockDim.x) {
        float o = (p[j] - mu) * r * w[j];
        out[row * (long)W + j] = RND ? tf32r(o) : o;
    }
}

// ---------------- causal depthwise conv (KS=4) + SiLU -> g_xc --------------
__global__ void conv_silu(const float* __restrict__ cw, const float* __restrict__ cb) {
    long idx = (long)blockIdx.x * blockDim.x + threadIdx.x;
    if (idx >= (long)ROWS * INNER) return;
    int  c   = (int)(idx & (INNER - 1));
    long row = idx >> 10;
    int  t   = (int)(row & (Ss - 1));
    float acc = cb[c];
    #pragma unroll
    for (int j = 0; j < KSk; ++j) {
        int dt = j - (KSk - 1);
        if (t + dt >= 0)
            acc += g_up[(row + dt) * (2 * INNER) + c] * cw[c * KSk + j];
    }
    g_xc[idx] = acc / (1.f + expf(-acc));
}

// ---------------- blockwise (4x4) q,k from xc; v from x_m (tf32-rounded) ---
__global__ void headwise(const float* __restrict__ Wq, const float* __restrict__ Wk,
                         const float* __restrict__ Wv) {
    long idx = (long)blockIdx.x * blockDim.x + threadIdx.x;    // ROWS*256
    if (idx >= (long)ROWS * 256) return;
    int  nb  = (int)(idx & 255);
    long row = idx >> 8;
    long base = row * INNER + nb * 4;
    float xc4[4], xm4[4];
    #pragma unroll
    for (int i = 0; i < 4; ++i) {
        xc4[i] = g_xc[base + i];
        xm4[i] = g_up[row * (2 * INNER) + nb * 4 + i];
    }
    #pragma unroll
    for (int o = 0; o < 4; ++o) {
        float q = 0.f, k = 0.f, v = 0.f;
        #pragma unroll
        for (int i = 0; i < 4; ++i) {
            q += xc4[i] * Wq[nb * 16 + o * 4 + i];
            k += xc4[i] * Wk[nb * 16 + o * 4 + i];
            v += xm4[i] * Wv[nb * 16 + o * 4 + i];
        }
        g_q[base + o] = tf32r(q); g_k[base + o] = tf32r(k); g_v[base + o] = tf32r(v);
    }
}

// ---------------- per-head v transpose: g_v -> g_vT[bn][d][s] ---------------
__global__ void transpose_v() {
    __shared__ float t[32][33];
    int bn = blockIdx.z;
    int s0 = blockIdx.x * 32, d0 = blockIdx.y * 32;
    int tx = threadIdx.x, ty = threadIdx.y;
    t[ty][tx] = g_v[((long)(bn >> 2) * Ss + s0 + ty) * INNER + (bn & 3) * DHd + d0 + tx];
    __syncthreads();
    g_vT[((long)bn * DHd + d0 + ty) * Ss + s0 + tx] = t[tx][ty];
}

// ---------------- input/forget gate projections -----------------------------
__global__ void gates(const float* __restrict__ Wig, const float* __restrict__ big,
                      const float* __restrict__ Wfg, const float* __restrict__ bfg) {
    long row = blockIdx.x;
    float aI[4] = {0, 0, 0, 0}, aF[4] = {0, 0, 0, 0};
    for (int c = threadIdx.x; c < INNER; c += blockDim.x) {
        float qv = g_q[row * INNER + c];
        float kv = g_k[row * INNER + c];
        float vv = g_v[row * INNER + c];
        #pragma unroll
        for (int n = 0; n < 4; ++n) {
            const float* wi = Wig + (long)n * 3 * INNER;
            const float* wf = Wfg + (long)n * 3 * INNER;
            aI[n] += qv * wi[c] + kv * wi[INNER + c] + vv * wi[2 * INNER + c];
            aF[n] += qv * wf[c] + kv * wf[INNER + c] + vv * wf[2 * INNER + c];
        }
    }
    int b = (int)(row >> 10), s = (int)(row & 1023);
    #pragma unroll
    for (int n = 0; n < 4; ++n) {
        float si = blockReduceSum(aI[n]);
        float sf = blockReduceSum(aF[n]);
        if (threadIdx.x == 0) {
            g_ig[(b * NHh + n) * Ss + s] = si + big[n];
            g_fg[(b * NHh + n) * Ss + s] = sf + bfg[n];
        }
    }
}

// ---------------- serial gate scan ------------------------------------------
__global__ void gate_scan() {
    int bn = threadIdx.x;
    if (bn >= BNH) return;
    float a = 0.f, pm = -1e30f;
    for (int t = 0; t < Ss; ++t) {
        float f  = g_fg[bn * Ss + t];
        float lf = fminf(f, 0.f) - log1pf(expf(-fabsf(f)));   // log_sigmoid
        a += lf;
        float e = g_ig[bn * Ss + t] - a;
        pm = fmaxf(pm, e);
        g_e [bn * Ss + t] = e;
        g_pm[bn * Ss + t] = pm;
        g_md[bn * Ss + t] = a + pm;
    }
}

// ---------------- apply decay D, mask, row-normalize (tf32-rounded out) ----
__global__ void dapply() {
    int s  = blockIdx.x;
    int bn = blockIdx.y;
    size_t base = ((size_t)bn * Ss + s) * Ss;
    float pm = g_pm[bn * Ss + s];
    const float scale = 0.0625f;   // 1/sqrt(DH)
    float vals[4];
    float sum = 0.f;
    #pragma unroll
    for (int l = 0; l < 4; ++l) {
        int t = threadIdx.x + l * 256;
        float v = 0.f;
        if (t <= s)
            v = g_C[base + t] * scale * expf(g_e[bn * Ss + t] - pm);
        vals[l] = v;
        sum += v;
    }
    sum = blockReduceSum(sum);
    float nn  = fmaxf(fabsf(sum), expf(-g_md[bn * Ss + s]));
    float inv = 1.f / (nn + 1e-6f);
    #pragma unroll
    for (int l = 0; l < 4; ++l)
        g_C[base + threadIdx.x + l * 256] = tf32r(vals[l] * inv);
}

// ---------------- per-head LN + skip + SiLU(z) gate (tf32-rounded out) -----
__global__ void mhln_combine(const float* __restrict__ mw, const float* __restrict__ skip) {
    int s  = blockIdx.x;
    int bn = blockIdx.y;
    int b = bn >> 2, n = bn & 3;
    int d = threadIdx.x;             // 256 == DH
    size_t hrow = ((size_t)bn * Ss + s) * DHd;
    float x  = g_hh[hrow + d];
    float su = blockReduceSum(x);
    float s2 = blockReduceSum(x * x);
    float mu  = su / DHd;
    float var = s2 / DHd - mu * mu;
    float hn = (x - mu) * rsqrtf(var + 1e-5f) * mw[n * DHd + d];
    int c = n * DHd + d;
    size_t row = (size_t)(b * Ss + s);
    float xc = g_xc[row * INNER + c];
    float z  = g_up[row * (2 * INNER) + INNER + c];
    float sz = z / (1.f + expf(-z));
    g_hs[row * INNER + c] = tf32r((hn + skip[c] * xc) * sz);
}

// ---------------- out = LN(res + y, ln_post_w) -> d_out --------------------
__global__ void add_ln_out(const float* __restrict__ w, float* __restrict__ out) {
    long row = blockIdx.x;
    float vals[2];
    float s = 0.f, s2 = 0.f;
    #pragma unroll
    for (int l = 0; l < 2; ++l) {
        int j = threadIdx.x + l * 256;
        float v = g_xp[row * Ee + j] + g_y[row * Ee + j];
        vals[l] = v; s += v; s2 += v * v;
    }
    s  = blockReduceSum(s);
    s2 = blockReduceSum(s2);
    float mu  = s / Ee;
    float var = s2 / Ee - mu * mu;
    float r = rsqrtf(var + 1e-5f);
    #pragma unroll
    for (int l = 0; l < 2; ++l) {
        int j = threadIdx.x + l * 256;
        out[row * Ee + j] = (vals[l] - mu) * r * w[j];
    }
}

// ---------------- launch ----------------------------------------------------
extern "C" void kernel_launch(void* const* d_in, const int* /*in_sizes*/, int /*n_in*/,
                              void* d_out, int /*out_size*/) {
    const float* x         = (const float*)d_in[0];
    const float* W_in      = (const float*)d_in[1];
    const float* b_in      = (const float*)d_in[2];
    const float* ln1_w     = (const float*)d_in[3];
    const float* W_up      = (const float*)d_in[4];
    const float* conv_w    = (const float*)d_in[5];
    const float* conv_b    = (const float*)d_in[6];
    const float* Wq        = (const float*)d_in[7];
    const float* Wk        = (const float*)d_in[8];
    const float* Wv        = (const float*)d_in[9];
    const float* W_ig      = (const float*)d_in[10];
    const float* b_ig      = (const float*)d_in[11];
    const float* W_fg      = (const float*)d_in[12];
    const float* b_fg      = (const float*)d_in[13];
    const float* mhln_w    = (const float*)d_in[14];
    const float* skip      = (const float*)d_in[15];
    const float* W_down    = (const float*)d_in[16];
    const float* ln_post_w = (const float*)d_in[17];
    float* out = (float*)d_out;

    void *pxp, *ph, *pup, *pxc, *pq, *pk, *pv, *pvT, *pC, *phh, *phs, *py;
    void *pxr, *pWi, *pWu, *pWd;
    cudaGetSymbolAddress(&pxp, g_xp);
    cudaGetSymbolAddress(&ph,  g_h);
    cudaGetSymbolAddress(&pup, g_up);
    cudaGetSymbolAddress(&pxc, g_xc);
    cudaGetSymbolAddress(&pq,  g_q);
    cudaGetSymbolAddress(&pk,  g_k);
    cudaGetSymbolAddress(&pv,  g_v);
    cudaGetSymbolAddress(&pvT, g_vT);
    cudaGetSymbolAddress(&pC,  g_C);
    cudaGetSymbolAddress(&phh, g_hh);
    cudaGetSymbolAddress(&phs, g_hs);
    cudaGetSymbolAddress(&py,  g_y);
    cudaGetSymbolAddress(&pxr, g_xr);
    cudaGetSymbolAddress(&pWi, g_Wi);
    cudaGetSymbolAddress(&pWu, g_Wu);
    cudaGetSymbolAddress(&pWd, g_Wd);

    cudaFuncSetAttribute(mma_gemm<0>, cudaFuncAttributeMaxDynamicSharedMemorySize, GSMEM);
    cudaFuncSetAttribute(mma_gemm<1>, cudaFuncAttributeMaxDynamicSharedMemorySize, GSMEM);
    cudaFuncSetAttribute(mma_gemm<2>, cudaFuncAttributeMaxDynamicSharedMemorySize, GSMEM);

    // 0. tf32-round GEMM operands we can't round in place
    roundbuf<<<(ROWS * FIN / 4 + 255) / 256, 256>>>(x, (float*)pxr, ROWS * FIN / 4);
    roundbuf<<<(Ee * FIN / 4 + 255) / 256, 256>>>(W_in, (float*)pWi, Ee * FIN / 4);
    roundbuf<<<(2 * INNER * Ee / 4 + 255) / 256, 256>>>(W_up, (float*)pWu, 2 * INNER * Ee / 4);
    roundbuf<<<(Ee * INNER / 4 + 255) / 256, 256>>>(W_down, (float*)pWd, Ee * INNER / 4);

    // 1. xp = x @ W_in^T + b_in        (M=8192, N=512, K=256)
    mma_gemm<0><<<dim3(Ee / 128, ROWS / 128, 1), 256, GSMEM>>>(
        (const float*)pxr, (const float*)pWi, (float*)pxp, b_in,
        FIN, FIN, FIN, Ee, 0, 0, 0, 0, 0, 0);

    // 2. h = LN(xp), rounded to tf32
    ln_rows<1><<<ROWS, 256>>>((const float*)pxp, ln1_w, (float*)ph, Ee);

    // 3. up = h @ W_up^T               (M=8192, N=2048, K=512)
    mma_gemm<0><<<dim3(2 * INNER / 128, ROWS / 128, 1), 256, GSMEM>>>(
        (const float*)ph, (const float*)pWu, (float*)pup, nullptr,
        Ee, Ee, Ee, 2 * INNER, 0, 0, 0, 0, 0, 0);

    // 4. xc = silu(causal_conv(x_m))
    conv_silu<<<(ROWS * INNER) / 256, 256>>>(conv_w, conv_b);

    // 5. q,k (from xc), v (from x_m), tf32-rounded
    headwise<<<(ROWS * 256) / 256, 256>>>(Wq, Wk, Wv);

    // 6. ig, fg gate projections
    gates<<<ROWS, 256>>>(W_ig, b_ig, W_fg, b_fg);

    // 7. gate scan
    gate_scan<<<1, 32>>>();

    // 7b. per-head v transpose for the C*V GEMM
    transpose_v<<<dim3(Ss / 32, DHd / 32, BNH), dim3(32, 32)>>>();

    // 8. C0 = q @ k^T per head (causal: skip upper-triangle blocks)
    mma_gemm<1><<<dim3(Ss / 128, Ss / 128, BNH), 256, GSMEM>>>(
        (const float*)pq, (const float*)pk, (float*)pC, nullptr,
        DHd, INNER, INNER, Ss,
        (long)Ss * INNER, (long)DHd,
        (long)Ss * INNER, (long)DHd,
        4L * Ss * Ss, (long)Ss * Ss);

    // 9. apply decay matrix, causal mask, normalizer (writes all of C)
    dapply<<<dim3(Ss, BNH), 256>>>();

    // 10. hh = Cn @ vT^T per head (K limited to causal extent per row-block)
    mma_gemm<2><<<dim3(DHd / 128, Ss / 128, BNH), 256, GSMEM>>>(
        (const float*)pC, (const float*)pvT, (float*)phh, nullptr,
        Ss, Ss, Ss, DHd,
        4L * Ss * Ss, (long)Ss * Ss,
        4L * DHd * Ss, (long)DHd * Ss,
        4L * Ss * DHd, (long)Ss * DHd);

    // 11. per-head LN + combine with skip*xc and silu(z), tf32-rounded
    mhln_combine<<<dim3(Ss, BNH), 256>>>(mhln_w, skip);

    // 12. y = h_state @ W_down^T       (M=8192, N=512, K=1024)
    mma_gemm<0><<<dim3(Ee / 128, ROWS / 128, 1), 256, GSMEM>>>(
        (const float*)phs, (const float*)pWd, (float*)py, nullptr,
        INNER, INNER, INNER, Ee, 0, 0, 0, 0, 0, 0);

    // 13. out = LN(res + y)
    add_ln_out<<<ROWS, 256>>>(ln_post_w, out);
}